// round 1
// baseline (speedup 1.0000x reference)
#include <cuda_runtime.h>
#include <math.h>

// Problem constants (fixed by the reference: B=65536, IN=256, G=512, WIDTH=512)
#define B_ROWS 65536
#define IN_DIM 256
#define G_DIM  512
#define W_DIM  512
#define LN_EPS 1e-5f

// Scratch (device globals — no allocation allowed in kernel_launch)
__device__ float g_scaled[(size_t)B_ROWS * G_DIM];    // 128 MB: RBF activations
__device__ float g_expanded[(size_t)B_ROWS * W_DIM];  // 128 MB: pre-LN linear output
__device__ float g_xsq[B_ROWS];
__device__ float g_csq[G_DIM];
__device__ float g_s[G_DIM];

// ---------------------------------------------------------------------------
// x_sq[b] = sum_i inputs[b,i]^2   (one warp per row)
// ---------------------------------------------------------------------------
__global__ __launch_bounds__(256) void xsq_kernel(const float* __restrict__ x) {
    int warp = (blockIdx.x * blockDim.x + threadIdx.x) >> 5;
    int lane = threadIdx.x & 31;
    if (warp >= B_ROWS) return;
    const float* row = x + (size_t)warp * IN_DIM;
    float acc = 0.f;
#pragma unroll
    for (int i = 0; i < IN_DIM / 32; i++) {
        float v = row[lane + 32 * i];
        acc = fmaf(v, v, acc);
    }
#pragma unroll
    for (int o = 16; o > 0; o >>= 1) acc += __shfl_xor_sync(0xffffffffu, acc, o);
    if (lane == 0) g_xsq[warp] = acc;
}

// ---------------------------------------------------------------------------
// c_sq[g] = sum_i centers[g,i]^2 ; s[g] = exp(log_scales[g])  (warp per center)
// ---------------------------------------------------------------------------
__global__ __launch_bounds__(256) void csq_kernel(const float* __restrict__ c,
                                                  const float* __restrict__ ls) {
    int warp = (blockIdx.x * blockDim.x + threadIdx.x) >> 5;
    int lane = threadIdx.x & 31;
    if (warp >= G_DIM) return;
    const float* row = c + (size_t)warp * IN_DIM;
    float acc = 0.f;
#pragma unroll
    for (int i = 0; i < IN_DIM / 32; i++) {
        float v = row[lane + 32 * i];
        acc = fmaf(v, v, acc);
    }
#pragma unroll
    for (int o = 16; o > 0; o >>= 1) acc += __shfl_xor_sync(0xffffffffu, acc, o);
    if (lane == 0) {
        g_csq[warp] = acc;
        g_s[warp] = expf(ls[warp]);
    }
}

// ---------------------------------------------------------------------------
// GEMM1 + RBF epilogue:
//   cross[m,g] = sum_k inputs[m,k] * centers[g,k]        (NT, K=256)
//   g_scaled[m,g] = exp(-(xsq[m] + csq[g] - 2*cross) * s[g])
// 128x128 CTA tile, BK=8, 256 threads, 8x8 per-thread microtile.
// ---------------------------------------------------------------------------
__global__ __launch_bounds__(256) void gemm1_kernel(const float* __restrict__ A,
                                                    const float* __restrict__ Cn) {
    __shared__ float As[8][128];
    __shared__ float Bs[8][128];
    const int m0 = blockIdx.y * 128;
    const int n0 = blockIdx.x * 128;
    const int tid = threadIdx.x;
    const int lr = tid >> 1;          // load row 0..127
    const int lc = (tid & 1) * 4;     // load col 0 or 4
    const int tx = tid & 15;          // microtile col group
    const int ty = tid >> 4;          // microtile row group

    float acc[8][8] = {};

    for (int k0 = 0; k0 < IN_DIM; k0 += 8) {
        float4 av = *(const float4*)(A  + (size_t)(m0 + lr) * IN_DIM + k0 + lc);
        float4 bv = *(const float4*)(Cn + (size_t)(n0 + lr) * IN_DIM + k0 + lc);
        As[lc + 0][lr] = av.x; As[lc + 1][lr] = av.y;
        As[lc + 2][lr] = av.z; As[lc + 3][lr] = av.w;
        Bs[lc + 0][lr] = bv.x; Bs[lc + 1][lr] = bv.y;
        Bs[lc + 2][lr] = bv.z; Bs[lc + 3][lr] = bv.w;
        __syncthreads();
#pragma unroll
        for (int k = 0; k < 8; k++) {
            float ra[8], rb[8];
#pragma unroll
            for (int i = 0; i < 8; i++) ra[i] = As[k][ty * 8 + i];
#pragma unroll
            for (int j = 0; j < 8; j++) rb[j] = Bs[k][tx * 8 + j];
#pragma unroll
            for (int i = 0; i < 8; i++)
#pragma unroll
                for (int j = 0; j < 8; j++)
                    acc[i][j] = fmaf(ra[i], rb[j], acc[i][j]);
        }
        __syncthreads();
    }

#pragma unroll
    for (int i = 0; i < 8; i++) {
        const int m = m0 + ty * 8 + i;
        const float xq = g_xsq[m];
#pragma unroll
        for (int j = 0; j < 8; j++) {
            const int g = n0 + tx * 8 + j;
            const float d2 = xq + g_csq[g] - 2.0f * acc[i][j];
            g_scaled[(size_t)m * G_DIM + g] = expf(-d2 * g_s[g]);
        }
    }
}

// ---------------------------------------------------------------------------
// GEMM2 + bias:
//   g_expanded[m,w] = sum_g g_scaled[m,g] * W[w,g] + b[w]   (NT, K=512)
// ---------------------------------------------------------------------------
__global__ __launch_bounds__(256) void gemm2_kernel(const float* __restrict__ W,
                                                    const float* __restrict__ b) {
    __shared__ float As[8][128];
    __shared__ float Bs[8][128];
    const int m0 = blockIdx.y * 128;
    const int n0 = blockIdx.x * 128;
    const int tid = threadIdx.x;
    const int lr = tid >> 1;
    const int lc = (tid & 1) * 4;
    const int tx = tid & 15;
    const int ty = tid >> 4;

    float acc[8][8] = {};

    for (int k0 = 0; k0 < G_DIM; k0 += 8) {
        float4 av = *(const float4*)(g_scaled + (size_t)(m0 + lr) * G_DIM + k0 + lc);
        float4 bv = *(const float4*)(W        + (size_t)(n0 + lr) * G_DIM + k0 + lc);
        As[lc + 0][lr] = av.x; As[lc + 1][lr] = av.y;
        As[lc + 2][lr] = av.z; As[lc + 3][lr] = av.w;
        Bs[lc + 0][lr] = bv.x; Bs[lc + 1][lr] = bv.y;
        Bs[lc + 2][lr] = bv.z; Bs[lc + 3][lr] = bv.w;
        __syncthreads();
#pragma unroll
        for (int k = 0; k < 8; k++) {
            float ra[8], rb[8];
#pragma unroll
            for (int i = 0; i < 8; i++) ra[i] = As[k][ty * 8 + i];
#pragma unroll
            for (int j = 0; j < 8; j++) rb[j] = Bs[k][tx * 8 + j];
#pragma unroll
            for (int i = 0; i < 8; i++)
#pragma unroll
                for (int j = 0; j < 8; j++)
                    acc[i][j] = fmaf(ra[i], rb[j], acc[i][j]);
        }
        __syncthreads();
    }

#pragma unroll
    for (int i = 0; i < 8; i++) {
        const int m = m0 + ty * 8 + i;
#pragma unroll
        for (int j = 0; j < 8; j++) {
            const int w = n0 + tx * 8 + j;
            g_expanded[(size_t)m * W_DIM + w] = acc[i][j] + b[w];
        }
    }
}

// ---------------------------------------------------------------------------
// LayerNorm(512) + tanh, one block (256 threads) per row.
// ---------------------------------------------------------------------------
__global__ __launch_bounds__(256) void ln_tanh_kernel(const float* __restrict__ gamma,
                                                      const float* __restrict__ beta,
                                                      float* __restrict__ out) {
    const int row = blockIdx.x;
    const float* e = g_expanded + (size_t)row * W_DIM;
    const int tid = threadIdx.x;

    float v0 = e[tid];
    float v1 = e[tid + 256];
    float s = v0 + v1;
    float sq = v0 * v0 + v1 * v1;
#pragma unroll
    for (int o = 16; o > 0; o >>= 1) {
        s  += __shfl_xor_sync(0xffffffffu, s,  o);
        sq += __shfl_xor_sync(0xffffffffu, sq, o);
    }
    __shared__ float ss[8], ssq[8];
    const int w = tid >> 5, l = tid & 31;
    if (l == 0) { ss[w] = s; ssq[w] = sq; }
    __syncthreads();
    if (w == 0) {
        s  = (l < 8) ? ss[l]  : 0.f;
        sq = (l < 8) ? ssq[l] : 0.f;
#pragma unroll
        for (int o = 4; o > 0; o >>= 1) {
            s  += __shfl_xor_sync(0xffffffffu, s,  o);
            sq += __shfl_xor_sync(0xffffffffu, sq, o);
        }
        if (l == 0) { ss[0] = s; ssq[0] = sq; }
    }
    __syncthreads();
    const float mean = ss[0] * (1.0f / W_DIM);
    const float var  = ssq[0] * (1.0f / W_DIM) - mean * mean;
    const float rstd = rsqrtf(var + LN_EPS);

    out[(size_t)row * W_DIM + tid]       = tanhf((v0 - mean) * rstd * gamma[tid]       + beta[tid]);
    out[(size_t)row * W_DIM + tid + 256] = tanhf((v1 - mean) * rstd * gamma[tid + 256] + beta[tid + 256]);
}

// ---------------------------------------------------------------------------
extern "C" void kernel_launch(void* const* d_in, const int* in_sizes, int n_in,
                              void* d_out, int out_size) {
    const float* inputs     = (const float*)d_in[0];  // (B, IN)
    const float* centers    = (const float*)d_in[1];  // (G, IN)
    const float* log_scales = (const float*)d_in[2];  // (G,)
    const float* W_mix      = (const float*)d_in[3];  // (WIDTH, G)
    const float* b_mix      = (const float*)d_in[4];  // (WIDTH,)
    const float* ln_gamma   = (const float*)d_in[5];  // (WIDTH,)
    const float* ln_beta    = (const float*)d_in[6];  // (WIDTH,)
    float* out = (float*)d_out;                       // (B, WIDTH)

    xsq_kernel<<<B_ROWS / 8, 256>>>(inputs);
    csq_kernel<<<G_DIM / 8, 256>>>(centers, log_scales);
    gemm1_kernel<<<dim3(G_DIM / 128, B_ROWS / 128), 256>>>(inputs, centers);
    gemm2_kernel<<<dim3(W_DIM / 128, B_ROWS / 128), 256>>>(W_mix, b_mix);
    ln_tanh_kernel<<<B_ROWS, 256>>>(ln_gamma, ln_beta, out);
}